// round 14
// baseline (speedup 1.0000x reference)
#include <cuda_runtime.h>
#include <cuda_fp16.h>
#include <math.h>
#include <stdint.h>

#define NN 50000
#define NE 800000
#define DD 64
#define GG 512
#define CHUNK 512
#define NCHUNK ((NN + CHUNK - 1) / CHUNK)   // 98

// -------- scratch (device globals; no allocation allowed) --------
__device__ uint32_t g_hA[NN * 32];   // activations as f16x2 pairs
__device__ uint32_t g_hB[NN * 32];
__device__ int   g_cnt[NN];
__device__ int   g_rowptr[NN + 1];
__device__ int   g_cursor[NN];
__device__ int   g_csr[NE];
__device__ int   g_chunksum[NCHUNK];
__device__ float g_pool[GG * DD];

__device__ __forceinline__ uint32_t pack2(float x, float y) {
    __half2 h = __floats2half2_rn(x, y);
    return *(uint32_t*)&h;
}
__device__ __forceinline__ float2 unpack2(uint32_t u) {
    return __half22float2(*(const __half2*)&u);
}
__device__ __forceinline__ void mma_f16(float c[4], const uint32_t a[4],
                                        const uint32_t b[2]) {
    asm volatile(
        "mma.sync.aligned.m16n8k16.row.col.f32.f16.f16.f32 "
        "{%0,%1,%2,%3}, {%4,%5,%6,%7}, {%8,%9}, {%0,%1,%2,%3};"
        : "+f"(c[0]), "+f"(c[1]), "+f"(c[2]), "+f"(c[3])
        : "r"(a[0]), "r"(a[1]), "r"(a[2]), "r"(a[3]), "r"(b[0]), "r"(b[1]));
}

// -------- CSR build --------
__global__ void k_zero() {
    int i = blockIdx.x * blockDim.x + threadIdx.x;
    if (i < NN) g_cnt[i] = 0;
    if (i < GG * DD) g_pool[i] = 0.f;
}

__global__ void k_count(const int* __restrict__ dst) {
    int e = blockIdx.x * blockDim.x + threadIdx.x;
    if (e < NE) atomicAdd(&g_cnt[dst[e]], 1);
}

__global__ void k_scanA() {
    __shared__ int wsum[16];
    int i = blockIdx.x * CHUNK + threadIdx.x;
    int lane = threadIdx.x & 31, w = threadIdx.x >> 5;
    int v = (i < NN) ? g_cnt[i] : 0;
    for (int off = 16; off > 0; off >>= 1)
        v += __shfl_down_sync(0xFFFFFFFF, v, off);
    if (lane == 0) wsum[w] = v;
    __syncthreads();
    if (w == 0) {
        int a = (lane < 16) ? wsum[lane] : 0;
        for (int off = 8; off > 0; off >>= 1)
            a += __shfl_down_sync(0xFFFFFFFF, a, off);
        if (lane == 0) g_chunksum[blockIdx.x] = a;
    }
}

__global__ void k_scanB() {
    __shared__ int wsum[16];
    __shared__ int s_pre;
    int bid = blockIdx.x, tx = threadIdx.x;
    int lane = tx & 31, w = tx >> 5;

    if (w == 0) {
        int a = 0;
        for (int j = lane; j < bid; j += 32) a += g_chunksum[j];
        for (int off = 16; off > 0; off >>= 1)
            a += __shfl_down_sync(0xFFFFFFFF, a, off);
        if (lane == 0) s_pre = a;
    }
    int i = bid * CHUNK + tx;
    int v = (i < NN) ? g_cnt[i] : 0;
    int sc = v;
    for (int off = 1; off < 32; off <<= 1) {
        int t = __shfl_up_sync(0xFFFFFFFF, sc, off);
        if (lane >= off) sc += t;
    }
    if (lane == 31) wsum[w] = sc;
    __syncthreads();
    if (w == 0) {
        int a = (lane < 16) ? wsum[lane] : 0;
        for (int off = 1; off < 16; off <<= 1) {
            int t = __shfl_up_sync(0xFFFFFFFF, a, off);
            if (lane >= off) a += t;
        }
        if (lane < 16) wsum[lane] = a;
    }
    __syncthreads();
    int excl = s_pre + ((w > 0) ? wsum[w - 1] : 0) + sc - v;
    if (i < NN) {
        g_rowptr[i] = excl;
        g_cursor[i] = excl;
    }
    if (bid == 0 && tx == 0) g_rowptr[NN] = NE;
}

__global__ void k_fill(const int* __restrict__ src, const int* __restrict__ dst) {
    int e = blockIdx.x * blockDim.x + threadIdx.x;
    if (e < NE) {
        int pos = atomicAdd(&g_cursor[dst[e]], 1);
        g_csr[pos] = src[e];
    }
}

// ========== fused layer: gather + GEMM (single-f16 mma) + epilogue ==========
// M=128 tile, 2 nodes/warp gather, 4 CTAs/SM. HADD2 accumulation in gather.
#define ASTR 68
#define A_U32 (128 * ASTR)           // 8704
#define B_U32 (64 * ASTR)            // 4352
#define SMEM_DYN ((A_U32 + B_U32) * 4)   // 52224 bytes

__global__ void __launch_bounds__(256, 4)
k_layer(const float* __restrict__ x, int insel, int outsel,
        const float* __restrict__ wrel,
        const float* __restrict__ wroot,
        const float* __restrict__ brel,
        int residual, int dopool, const int* __restrict__ batch) {
    const uint32_t* hinh = (insel == 1) ? g_hA : g_hB;
    uint32_t* hout = (outsel == 1) ? g_hA : g_hB;

    extern __shared__ uint32_t sm[];
    uint32_t* Ah = sm;
    uint32_t* Bh = sm + A_U32;

    int tid = threadIdx.x;
    int wid = tid >> 5;
    int lid = tid & 31;
    int g = lid >> 2;            // 0..7
    int t = lid & 3;             // 0..3
    int m0 = blockIdx.x * 128;

    // ---- stage B = [Wrel | Wroot] as f16 ----
#pragma unroll
    for (int i = 0; i < 8; i++) {
        int idx = i * 256 + tid;          // 0..2047
        int n = idx >> 5;                 // 0..63
        int kp = idx & 31;                // pair col (k = 2kp)
        float2 v0 = *(const float2*)&wrel[n * DD + 2 * kp];
        float2 v1 = *(const float2*)&wroot[n * DD + 2 * kp];
        Bh[n * ASTR + kp]      = pack2(v0.x, v0.y);
        Bh[n * ASTR + 32 + kp] = pack2(v1.x, v1.y);
    }

    // ---- gather + stage A = [agg | h] (single f16) ----
    {
        int lid16 = tid & 15;         // lane within node group
        int sub = tid >> 4;           // node slot 0..15
        int qq = lid16 & 7;           // uint4 slot within 128B row
        int parity = lid16 >> 3;      // which edge parity this lane sums
#pragma unroll
        for (int it = 0; it < 8; it++) {
            int mloc = it * 16 + sub;           // 0..127
            int m = m0 + mloc;
            if (insel == 0) {
                // layer 0: gather fp32 x (16 lanes/node, float4 each)
                int q = lid16;
                float ax = 0.f, ay = 0.f, az = 0.f, aw = 0.f;
                uint32_t hp0 = 0, hp1 = 0;
                if (m < NN) {
                    int s0 = g_rowptr[m];
                    int s1 = g_rowptr[m + 1];
                    float4 a0 = make_float4(0.f, 0.f, 0.f, 0.f);
                    float4 a1 = a0, a2 = a0, a3 = a0;
                    int e = s0;
                    int e4 = s0 + ((s1 - s0) & ~3);
                    for (; e < e4; e += 4) {
                        int i0 = __ldg(&g_csr[e + 0]);
                        int i1 = __ldg(&g_csr[e + 1]);
                        int i2 = __ldg(&g_csr[e + 2]);
                        int i3 = __ldg(&g_csr[e + 3]);
                        float4 v0 = __ldg((const float4*)&x[i0 * DD + q * 4]);
                        float4 v1 = __ldg((const float4*)&x[i1 * DD + q * 4]);
                        float4 v2 = __ldg((const float4*)&x[i2 * DD + q * 4]);
                        float4 v3 = __ldg((const float4*)&x[i3 * DD + q * 4]);
                        a0.x += v0.x; a0.y += v0.y; a0.z += v0.z; a0.w += v0.w;
                        a1.x += v1.x; a1.y += v1.y; a1.z += v1.z; a1.w += v1.w;
                        a2.x += v2.x; a2.y += v2.y; a2.z += v2.z; a2.w += v2.w;
                        a3.x += v3.x; a3.y += v3.y; a3.z += v3.z; a3.w += v3.w;
                    }
                    for (; e < s1; e++) {
                        int i0 = __ldg(&g_csr[e]);
                        float4 v0 = __ldg((const float4*)&x[i0 * DD + q * 4]);
                        a0.x += v0.x; a0.y += v0.y; a0.z += v0.z; a0.w += v0.w;
                    }
                    ax = (a0.x + a1.x) + (a2.x + a3.x);
                    ay = (a0.y + a1.y) + (a2.y + a3.y);
                    az = (a0.z + a1.z) + (a2.z + a3.z);
                    aw = (a0.w + a1.w) + (a2.w + a3.w);
                    float4 h4 = __ldg((const float4*)&x[m * DD + q * 4]);
                    hp0 = pack2(h4.x, h4.y);
                    hp1 = pack2(h4.z, h4.w);
                }
                Ah[mloc * ASTR + 2 * q]     = pack2(ax, ay);
                Ah[mloc * ASTR + 2 * q + 1] = pack2(az, aw);
                Ah[mloc * ASTR + 32 + 2 * q]     = hp0;
                Ah[mloc * ASTR + 32 + 2 * q + 1] = hp1;
            } else {
                // f16 layers: parity-split LDG.128 gather, HADD2 accumulation
                __half2 za = __float2half2_rn(0.f);
                __half2 accA[4] = {za, za, za, za};
                __half2 accB[4] = {za, za, za, za};
                if (m < NN) {
                    int s0 = g_rowptr[m];
                    int s1 = g_rowptr[m + 1];
                    int e = s0 + parity;
                    // 4 edges in flight per lane (stride-2 parity stream)
                    for (; e + 6 < s1; e += 8) {
                        int i0 = __ldg(&g_csr[e]);
                        int i1 = __ldg(&g_csr[e + 2]);
                        int i2 = __ldg(&g_csr[e + 4]);
                        int i3 = __ldg(&g_csr[e + 6]);
                        uint4 u0 = __ldg((const uint4*)&hinh[i0 * 32 + 4 * qq]);
                        uint4 u1 = __ldg((const uint4*)&hinh[i1 * 32 + 4 * qq]);
                        uint4 u2 = __ldg((const uint4*)&hinh[i2 * 32 + 4 * qq]);
                        uint4 u3 = __ldg((const uint4*)&hinh[i3 * 32 + 4 * qq]);
                        accA[0] = __hadd2(accA[0], *(__half2*)&u0.x);
                        accA[1] = __hadd2(accA[1], *(__half2*)&u0.y);
                        accA[2] = __hadd2(accA[2], *(__half2*)&u0.z);
                        accA[3] = __hadd2(accA[3], *(__half2*)&u0.w);
                        accB[0] = __hadd2(accB[0], *(__half2*)&u1.x);
                        accB[1] = __hadd2(accB[1], *(__half2*)&u1.y);
                        accB[2] = __hadd2(accB[2], *(__half2*)&u1.z);
                        accB[3] = __hadd2(accB[3], *(__half2*)&u1.w);
                        accA[0] = __hadd2(accA[0], *(__half2*)&u2.x);
                        accA[1] = __hadd2(accA[1], *(__half2*)&u2.y);
                        accA[2] = __hadd2(accA[2], *(__half2*)&u2.z);
                        accA[3] = __hadd2(accA[3], *(__half2*)&u2.w);
                        accB[0] = __hadd2(accB[0], *(__half2*)&u3.x);
                        accB[1] = __hadd2(accB[1], *(__half2*)&u3.y);
                        accB[2] = __hadd2(accB[2], *(__half2*)&u3.z);
                        accB[3] = __hadd2(accB[3], *(__half2*)&u3.w);
                    }
                    for (; e < s1; e += 2) {
                        int i0 = __ldg(&g_csr[e]);
                        uint4 u0 = __ldg((const uint4*)&hinh[i0 * 32 + 4 * qq]);
                        accA[0] = __hadd2(accA[0], *(__half2*)&u0.x);
                        accA[1] = __hadd2(accA[1], *(__half2*)&u0.y);
                        accA[2] = __hadd2(accA[2], *(__half2*)&u0.z);
                        accA[3] = __hadd2(accA[3], *(__half2*)&u0.w);
                    }
                }
                // convert to f32, combine both unroll sets + parity halves
                float acc8[8];
#pragma unroll
                for (int c = 0; c < 4; c++) {
                    float2 fa = __half22float2(accA[c]);
                    float2 fb = __half22float2(accB[c]);
                    acc8[2 * c]     = fa.x + fb.x;
                    acc8[2 * c + 1] = fa.y + fb.y;
                }
#pragma unroll
                for (int c = 0; c < 8; c++)
                    acc8[c] += __shfl_xor_sync(0xFFFFFFFF, acc8[c], 8);
                uint32_t* arow = &Ah[mloc * ASTR];
                if (parity == 0) {
                    arow[4 * qq + 0] = pack2(acc8[0], acc8[1]);
                    arow[4 * qq + 1] = pack2(acc8[2], acc8[3]);
                    arow[4 * qq + 2] = pack2(acc8[4], acc8[5]);
                    arow[4 * qq + 3] = pack2(acc8[6], acc8[7]);
                } else {
                    uint4 hu = make_uint4(0, 0, 0, 0);
                    if (m < NN) hu = __ldg((const uint4*)&hinh[m * 32 + 4 * qq]);
                    arow[32 + 4 * qq + 0] = hu.x;
                    arow[32 + 4 * qq + 1] = hu.y;
                    arow[32 + 4 * qq + 2] = hu.z;
                    arow[32 + 4 * qq + 3] = hu.w;
                }
            }
        }
    }
    __syncthreads();

    // ---- mma mainloop: single product, warp wid owns rows [wid*16,+16) ----
    float acc[8][4];
#pragma unroll
    for (int nf = 0; nf < 8; nf++)
#pragma unroll
        for (int c = 0; c < 4; c++) acc[nf][c] = 0.f;

    int ar0 = (wid * 16 + g) * ASTR;
    int ar1 = (wid * 16 + g + 8) * ASTR;

#pragma unroll
    for (int ks = 0; ks < 8; ks++) {
        int kc = ks * 8;
        uint32_t ah[4];
        ah[0] = Ah[ar0 + kc + t];
        ah[1] = Ah[ar1 + kc + t];
        ah[2] = Ah[ar0 + kc + t + 4];
        ah[3] = Ah[ar1 + kc + t + 4];
#pragma unroll
        for (int nf = 0; nf < 8; nf++) {
            int nb = (nf * 8 + g) * ASTR + kc;
            uint32_t bh[2];
            bh[0] = Bh[nb + t];
            bh[1] = Bh[nb + t + 4];
            mma_f16(acc[nf], ah, bh);
        }
    }

    // ---- epilogue: bias + residual + relu + (pool | store f16) ----
    int r0 = m0 + wid * 16 + g;
    int r1 = r0 + 8;
#pragma unroll
    for (int nf = 0; nf < 8; nf++) {
        int col = nf * 8 + t * 2;
        float b0 = __ldg(&brel[col]);
        float b1 = __ldg(&brel[col + 1]);
#pragma unroll
        for (int half = 0; half < 2; half++) {
            int m = half ? r1 : r0;
            if (m >= NN) continue;
            float v0 = acc[nf][half * 2 + 0] + b0;
            float v1 = acc[nf][half * 2 + 1] + b1;
            if (residual) {
                float2 h2 = unpack2(hinh[m * 32 + (col >> 1)]);
                v0 += h2.x; v1 += h2.y;
            }
            v0 = fmaxf(v0, 0.f);
            v1 = fmaxf(v1, 0.f);
            if (dopool) {
                int b = __ldg(&batch[m]);
                atomicAdd(&g_pool[b * DD + col + 0], v0);
                atomicAdd(&g_pool[b * DD + col + 1], v1);
            } else {
                hout[m * 32 + (col >> 1)] = pack2(v0, v1);
            }
        }
    }
}

// -------- final linear + softmax (counts via binary search on sorted batch) --
__global__ void k_final(const float* __restrict__ lin_w,
                        const float* __restrict__ lin_b,
                        const int* __restrict__ batch,
                        float* __restrict__ out) {
    __shared__ float sw[64 * 65];
    __shared__ float p[64];
    __shared__ float red[64];
    __shared__ float s_cnt;
    int g = blockIdx.x;
    int j = threadIdx.x;

    if (j == 0) {
        int lo = 0, hi = NN;
        while (lo < hi) { int mid = (lo + hi) >> 1; if (__ldg(&batch[mid]) < g) lo = mid + 1; else hi = mid; }
        int a = lo;
        lo = 0; hi = NN;
        while (lo < hi) { int mid = (lo + hi) >> 1; if (__ldg(&batch[mid]) <= g) lo = mid + 1; else hi = mid; }
        s_cnt = fmaxf((float)(lo - a), 1.f);
    }

    for (int r = 0; r < 64; r++) sw[j * 65 + r] = lin_w[r * 64 + j];
    __syncthreads();

    p[j] = g_pool[g * DD + j] / s_cnt;
    __syncthreads();

    float acc = lin_b[j];
#pragma unroll
    for (int k = 0; k < 64; k++) acc += p[k] * sw[k * 65 + j];

    red[j] = acc;
    __syncthreads();
    for (int s = 32; s > 0; s >>= 1) {
        if (j < s) red[j] = fmaxf(red[j], red[j + s]);
        __syncthreads();
    }
    float mx = red[0];
    __syncthreads();
    float e = expf(acc - mx);
    red[j] = e;
    __syncthreads();
    for (int s = 32; s > 0; s >>= 1) {
        if (j < s) red[j] += red[j + s];
        __syncthreads();
    }
    out[g * DD + j] = e / red[0];
}

extern "C" void kernel_launch(void* const* d_in, const int* in_sizes, int n_in,
                              void* d_out, int out_size) {
    const float* x      = (const float*)d_in[0];
    const int*   ei     = (const int*)d_in[1];
    const int*   batch  = (const int*)d_in[2];
    const float* rel_w  = (const float*)d_in[3];
    const float* rel_b  = (const float*)d_in[4];
    const float* root_w = (const float*)d_in[5];
    const float* lin_w  = (const float*)d_in[6];
    const float* lin_b  = (const float*)d_in[7];
    float* out = (float*)d_out;

    cudaFuncSetAttribute(k_layer, cudaFuncAttributeMaxDynamicSharedMemorySize,
                         SMEM_DYN);

    const int* src = ei;
    const int* dst = ei + NE;

    k_zero<<<(NN + 255) / 256, 256>>>();   // covers NN and GG*DD
    k_count<<<(NE + 255) / 256, 256>>>(dst);
    k_scanA<<<NCHUNK, CHUNK>>>();
    k_scanB<<<NCHUNK, CHUNK>>>();
    k_fill<<<(NE + 255) / 256, 256>>>(src, dst);

    int insel = 0;
    for (int l = 0; l < 5; l++) {
        int outsel = (insel == 1) ? 2 : 1;
        k_layer<<<(NN + 127) / 128, 256, SMEM_DYN>>>(
            x, insel, outsel,
            rel_w + l * DD * DD,
            root_w + l * DD * DD,
            rel_b + l * DD,
            (l >= 3) ? 1 : 0,
            (l == 4) ? 1 : 0,
            batch);
        insel = outsel;
    }

    k_final<<<GG, DD>>>(lin_w, lin_b, batch, out);
}

// round 15
// speedup vs baseline: 1.4167x; 1.4167x over previous
#include <cuda_runtime.h>
#include <cuda_fp16.h>
#include <math.h>
#include <stdint.h>

#define NN 50000
#define NE 800000
#define DD 64
#define GG 512
#define CHUNK 512
#define NCHUNK ((NN + CHUNK - 1) / CHUNK)   // 98

// -------- scratch (device globals; no allocation allowed) --------
__device__ uint32_t g_hA[NN * 32];   // activations as f16x2 pairs
__device__ uint32_t g_hB[NN * 32];
__device__ int      g_cnt[NN];
__device__ int      g_rowptr[NN + 1];
__device__ int      g_cursor[NN];
__device__ uint16_t g_csr[NE];       // node ids < 65536
__device__ int      g_chunksum[NCHUNK];
__device__ float    g_pool[GG * DD];

__device__ __forceinline__ uint32_t pack2(float x, float y) {
    __half2 h = __floats2half2_rn(x, y);
    return *(uint32_t*)&h;
}
__device__ __forceinline__ float2 unpack2(uint32_t u) {
    return __half22float2(*(const __half2*)&u);
}
__device__ __forceinline__ void mma_f16(float c[4], const uint32_t a[4],
                                        const uint32_t b[2]) {
    asm volatile(
        "mma.sync.aligned.m16n8k16.row.col.f32.f16.f16.f32 "
        "{%0,%1,%2,%3}, {%4,%5,%6,%7}, {%8,%9}, {%0,%1,%2,%3};"
        : "+f"(c[0]), "+f"(c[1]), "+f"(c[2]), "+f"(c[3])
        : "r"(a[0]), "r"(a[1]), "r"(a[2]), "r"(a[3]), "r"(b[0]), "r"(b[1]));
}

// -------- CSR build --------
__global__ void k_zero() {
    int i = blockIdx.x * blockDim.x + threadIdx.x;
    if (i < NN) g_cnt[i] = 0;
    if (i < GG * DD) g_pool[i] = 0.f;
}

__global__ void k_count(const int* __restrict__ dst) {
    int e = blockIdx.x * blockDim.x + threadIdx.x;
    if (e < NE) atomicAdd(&g_cnt[dst[e]], 1);
}

__global__ void k_scanA() {
    __shared__ int wsum[16];
    int i = blockIdx.x * CHUNK + threadIdx.x;
    int lane = threadIdx.x & 31, w = threadIdx.x >> 5;
    int v = (i < NN) ? g_cnt[i] : 0;
    for (int off = 16; off > 0; off >>= 1)
        v += __shfl_down_sync(0xFFFFFFFF, v, off);
    if (lane == 0) wsum[w] = v;
    __syncthreads();
    if (w == 0) {
        int a = (lane < 16) ? wsum[lane] : 0;
        for (int off = 8; off > 0; off >>= 1)
            a += __shfl_down_sync(0xFFFFFFFF, a, off);
        if (lane == 0) g_chunksum[blockIdx.x] = a;
    }
}

__global__ void k_scanB() {
    __shared__ int wsum[16];
    __shared__ int s_pre;
    int bid = blockIdx.x, tx = threadIdx.x;
    int lane = tx & 31, w = tx >> 5;

    if (w == 0) {
        int a = 0;
        for (int j = lane; j < bid; j += 32) a += g_chunksum[j];
        for (int off = 16; off > 0; off >>= 1)
            a += __shfl_down_sync(0xFFFFFFFF, a, off);
        if (lane == 0) s_pre = a;
    }
    int i = bid * CHUNK + tx;
    int v = (i < NN) ? g_cnt[i] : 0;
    int sc = v;
    for (int off = 1; off < 32; off <<= 1) {
        int t = __shfl_up_sync(0xFFFFFFFF, sc, off);
        if (lane >= off) sc += t;
    }
    if (lane == 31) wsum[w] = sc;
    __syncthreads();
    if (w == 0) {
        int a = (lane < 16) ? wsum[lane] : 0;
        for (int off = 1; off < 16; off <<= 1) {
            int t = __shfl_up_sync(0xFFFFFFFF, a, off);
            if (lane >= off) a += t;
        }
        if (lane < 16) wsum[lane] = a;
    }
    __syncthreads();
    int excl = s_pre + ((w > 0) ? wsum[w - 1] : 0) + sc - v;
    if (i < NN) {
        g_rowptr[i] = excl;
        g_cursor[i] = excl;
    }
    if (bid == 0 && tx == 0) g_rowptr[NN] = NE;
}

__global__ void k_fill(const int* __restrict__ src, const int* __restrict__ dst) {
    int e = blockIdx.x * blockDim.x + threadIdx.x;
    if (e < NE) {
        int pos = atomicAdd(&g_cursor[dst[e]], 1);
        g_csr[pos] = (uint16_t)src[e];
    }
}

// ========== fused layer: gather + GEMM (single-f16 mma) + epilogue ==========
// M=128 tile, 2 nodes/warp gather, 3 CTAs/SM. ONE HMMA product per frag.
#define ASTR 68
#define A_U32 (128 * ASTR)           // 8704
#define B_U32 (64 * ASTR)            // 4352
#define SMEM_DYN ((A_U32 + B_U32) * 4)   // 52224 bytes

__global__ void __launch_bounds__(256, 3)
k_layer(const float* __restrict__ x, int insel, int outsel,
        const float* __restrict__ wrel,
        const float* __restrict__ wroot,
        const float* __restrict__ brel,
        int residual, int dopool, const int* __restrict__ batch) {
    const uint32_t* hinh = (insel == 1) ? g_hA : g_hB;
    uint32_t* hout = (outsel == 1) ? g_hA : g_hB;

    extern __shared__ uint32_t sm[];
    uint32_t* Ah = sm;
    uint32_t* Bh = sm + A_U32;

    int tid = threadIdx.x;
    int wid = tid >> 5;
    int lid = tid & 31;
    int g = lid >> 2;            // 0..7
    int t = lid & 3;             // 0..3
    int m0 = blockIdx.x * 128;

    // ---- stage B = [Wrel | Wroot] as f16 ----
#pragma unroll
    for (int i = 0; i < 8; i++) {
        int idx = i * 256 + tid;          // 0..2047
        int n = idx >> 5;                 // 0..63
        int kp = idx & 31;                // pair col (k = 2kp)
        float2 v0 = *(const float2*)&wrel[n * DD + 2 * kp];
        float2 v1 = *(const float2*)&wroot[n * DD + 2 * kp];
        Bh[n * ASTR + kp]      = pack2(v0.x, v0.y);
        Bh[n * ASTR + 32 + kp] = pack2(v1.x, v1.y);
    }

    // ---- gather + stage A = [agg | h] (single f16) ----
    {
        int lid16 = tid & 15;         // lane within node group
        int sub = tid >> 4;           // node slot 0..15
        int qq = lid16 & 7;           // uint4 slot within 128B row
        int parity = lid16 >> 3;      // which edge parity this lane sums
#pragma unroll
        for (int it = 0; it < 8; it++) {
            int mloc = it * 16 + sub;           // 0..127
            int m = m0 + mloc;
            if (insel == 0) {
                // layer 0: gather fp32 x (16 lanes/node, float4 each)
                int q = lid16;
                float ax = 0.f, ay = 0.f, az = 0.f, aw = 0.f;
                uint32_t hp0 = 0, hp1 = 0;
                if (m < NN) {
                    int s0 = g_rowptr[m];
                    int s1 = g_rowptr[m + 1];
                    float4 a0 = make_float4(0.f, 0.f, 0.f, 0.f);
                    float4 a1 = a0, a2 = a0, a3 = a0;
                    int e = s0;
                    int e4 = s0 + ((s1 - s0) & ~3);
                    for (; e < e4; e += 4) {
                        int i0 = (int)__ldg(&g_csr[e + 0]);
                        int i1 = (int)__ldg(&g_csr[e + 1]);
                        int i2 = (int)__ldg(&g_csr[e + 2]);
                        int i3 = (int)__ldg(&g_csr[e + 3]);
                        float4 v0 = __ldg((const float4*)&x[i0 * DD + q * 4]);
                        float4 v1 = __ldg((const float4*)&x[i1 * DD + q * 4]);
                        float4 v2 = __ldg((const float4*)&x[i2 * DD + q * 4]);
                        float4 v3 = __ldg((const float4*)&x[i3 * DD + q * 4]);
                        a0.x += v0.x; a0.y += v0.y; a0.z += v0.z; a0.w += v0.w;
                        a1.x += v1.x; a1.y += v1.y; a1.z += v1.z; a1.w += v1.w;
                        a2.x += v2.x; a2.y += v2.y; a2.z += v2.z; a2.w += v2.w;
                        a3.x += v3.x; a3.y += v3.y; a3.z += v3.z; a3.w += v3.w;
                    }
                    for (; e < s1; e++) {
                        int i0 = (int)__ldg(&g_csr[e]);
                        float4 v0 = __ldg((const float4*)&x[i0 * DD + q * 4]);
                        a0.x += v0.x; a0.y += v0.y; a0.z += v0.z; a0.w += v0.w;
                    }
                    ax = (a0.x + a1.x) + (a2.x + a3.x);
                    ay = (a0.y + a1.y) + (a2.y + a3.y);
                    az = (a0.z + a1.z) + (a2.z + a3.z);
                    aw = (a0.w + a1.w) + (a2.w + a3.w);
                    float4 h4 = __ldg((const float4*)&x[m * DD + q * 4]);
                    hp0 = pack2(h4.x, h4.y);
                    hp1 = pack2(h4.z, h4.w);
                }
                Ah[mloc * ASTR + 2 * q]     = pack2(ax, ay);
                Ah[mloc * ASTR + 2 * q + 1] = pack2(az, aw);
                Ah[mloc * ASTR + 32 + 2 * q]     = hp0;
                Ah[mloc * ASTR + 32 + 2 * q + 1] = hp1;
            } else {
                // f16 layers: parity-split LDG.128 gather (fp32 accumulate)
                float acc8[8];
#pragma unroll
                for (int c = 0; c < 8; c++) acc8[c] = 0.f;
                if (m < NN) {
                    int s0 = g_rowptr[m];
                    int s1 = g_rowptr[m + 1];
                    int e = s0 + parity;
                    for (; e + 2 < s1; e += 4) {
                        int i0 = (int)__ldg(&g_csr[e]);
                        int i1 = (int)__ldg(&g_csr[e + 2]);
                        uint4 u0 = __ldg((const uint4*)&hinh[i0 * 32 + 4 * qq]);
                        uint4 u1 = __ldg((const uint4*)&hinh[i1 * 32 + 4 * qq]);
                        float2 f;
                        f = unpack2(u0.x); acc8[0] += f.x; acc8[1] += f.y;
                        f = unpack2(u0.y); acc8[2] += f.x; acc8[3] += f.y;
                        f = unpack2(u0.z); acc8[4] += f.x; acc8[5] += f.y;
                        f = unpack2(u0.w); acc8[6] += f.x; acc8[7] += f.y;
                        f = unpack2(u1.x); acc8[0] += f.x; acc8[1] += f.y;
                        f = unpack2(u1.y); acc8[2] += f.x; acc8[3] += f.y;
                        f = unpack2(u1.z); acc8[4] += f.x; acc8[5] += f.y;
                        f = unpack2(u1.w); acc8[6] += f.x; acc8[7] += f.y;
                    }
                    for (; e < s1; e += 2) {
                        int i0 = (int)__ldg(&g_csr[e]);
                        uint4 u0 = __ldg((const uint4*)&hinh[i0 * 32 + 4 * qq]);
                        float2 f;
                        f = unpack2(u0.x); acc8[0] += f.x; acc8[1] += f.y;
                        f = unpack2(u0.y); acc8[2] += f.x; acc8[3] += f.y;
                        f = unpack2(u0.z); acc8[4] += f.x; acc8[5] += f.y;
                        f = unpack2(u0.w); acc8[6] += f.x; acc8[7] += f.y;
                    }
                }
#pragma unroll
                for (int c = 0; c < 8; c++)
                    acc8[c] += __shfl_xor_sync(0xFFFFFFFF, acc8[c], 8);
                uint32_t* arow = &Ah[mloc * ASTR];
                if (parity == 0) {
                    arow[4 * qq + 0] = pack2(acc8[0], acc8[1]);
                    arow[4 * qq + 1] = pack2(acc8[2], acc8[3]);
                    arow[4 * qq + 2] = pack2(acc8[4], acc8[5]);
                    arow[4 * qq + 3] = pack2(acc8[6], acc8[7]);
                } else {
                    uint4 hu = make_uint4(0, 0, 0, 0);
                    if (m < NN) hu = __ldg((const uint4*)&hinh[m * 32 + 4 * qq]);
                    arow[32 + 4 * qq + 0] = hu.x;
                    arow[32 + 4 * qq + 1] = hu.y;
                    arow[32 + 4 * qq + 2] = hu.z;
                    arow[32 + 4 * qq + 3] = hu.w;
                }
            }
        }
    }
    __syncthreads();

    // ---- mma mainloop: single product, warp wid owns rows [wid*16,+16) ----
    float acc[8][4];
#pragma unroll
    for (int nf = 0; nf < 8; nf++)
#pragma unroll
        for (int c = 0; c < 4; c++) acc[nf][c] = 0.f;

    int ar0 = (wid * 16 + g) * ASTR;
    int ar1 = (wid * 16 + g + 8) * ASTR;

#pragma unroll
    for (int ks = 0; ks < 8; ks++) {
        int kc = ks * 8;
        uint32_t ah[4];
        ah[0] = Ah[ar0 + kc + t];
        ah[1] = Ah[ar1 + kc + t];
        ah[2] = Ah[ar0 + kc + t + 4];
        ah[3] = Ah[ar1 + kc + t + 4];
#pragma unroll
        for (int nf = 0; nf < 8; nf++) {
            int nb = (nf * 8 + g) * ASTR + kc;
            uint32_t bh[2];
            bh[0] = Bh[nb + t];
            bh[1] = Bh[nb + t + 4];
            mma_f16(acc[nf], ah, bh);
        }
    }

    // ---- epilogue: bias + residual + relu + (pool | store f16) ----
    int r0 = m0 + wid * 16 + g;
    int r1 = r0 + 8;
#pragma unroll
    for (int nf = 0; nf < 8; nf++) {
        int col = nf * 8 + t * 2;
        float b0 = __ldg(&brel[col]);
        float b1 = __ldg(&brel[col + 1]);
#pragma unroll
        for (int half = 0; half < 2; half++) {
            int m = half ? r1 : r0;
            if (m >= NN) continue;
            float v0 = acc[nf][half * 2 + 0] + b0;
            float v1 = acc[nf][half * 2 + 1] + b1;
            if (residual) {
                float2 h2 = unpack2(hinh[m * 32 + (col >> 1)]);
                v0 += h2.x; v1 += h2.y;
            }
            v0 = fmaxf(v0, 0.f);
            v1 = fmaxf(v1, 0.f);
            if (dopool) {
                int b = __ldg(&batch[m]);
                atomicAdd(&g_pool[b * DD + col + 0], v0);
                atomicAdd(&g_pool[b * DD + col + 1], v1);
            } else {
                hout[m * 32 + (col >> 1)] = pack2(v0, v1);
            }
        }
    }
}

// -------- final linear + softmax (counts via binary search on sorted batch) --
__global__ void k_final(const float* __restrict__ lin_w,
                        const float* __restrict__ lin_b,
                        const int* __restrict__ batch,
                        float* __restrict__ out) {
    __shared__ float sw[64 * 65];
    __shared__ float p[64];
    __shared__ float red[64];
    __shared__ float s_cnt;
    int g = blockIdx.x;
    int j = threadIdx.x;

    if (j == 0) {
        int lo = 0, hi = NN;
        while (lo < hi) { int mid = (lo + hi) >> 1; if (__ldg(&batch[mid]) < g) lo = mid + 1; else hi = mid; }
        int a = lo;
        lo = 0; hi = NN;
        while (lo < hi) { int mid = (lo + hi) >> 1; if (__ldg(&batch[mid]) <= g) lo = mid + 1; else hi = mid; }
        s_cnt = fmaxf((float)(lo - a), 1.f);
    }

    for (int r = 0; r < 64; r++) sw[j * 65 + r] = lin_w[r * 64 + j];
    __syncthreads();

    p[j] = g_pool[g * DD + j] / s_cnt;
    __syncthreads();

    float acc = lin_b[j];
#pragma unroll
    for (int k = 0; k < 64; k++) acc += p[k] * sw[k * 65 + j];

    red[j] = acc;
    __syncthreads();
    for (int s = 32; s > 0; s >>= 1) {
        if (j < s) red[j] = fmaxf(red[j], red[j + s]);
        __syncthreads();
    }
    float mx = red[0];
    __syncthreads();
    float e = expf(acc - mx);
    red[j] = e;
    __syncthreads();
    for (int s = 32; s > 0; s >>= 1) {
        if (j < s) red[j] += red[j + s];
        __syncthreads();
    }
    out[g * DD + j] = e / red[0];
}

extern "C" void kernel_launch(void* const* d_in, const int* in_sizes, int n_in,
                              void* d_out, int out_size) {
    const float* x      = (const float*)d_in[0];
    const int*   ei     = (const int*)d_in[1];
    const int*   batch  = (const int*)d_in[2];
    const float* rel_w  = (const float*)d_in[3];
    const float* rel_b  = (const float*)d_in[4];
    const float* root_w = (const float*)d_in[5];
    const float* lin_w  = (const float*)d_in[6];
    const float* lin_b  = (const float*)d_in[7];
    float* out = (float*)d_out;

    cudaFuncSetAttribute(k_layer, cudaFuncAttributeMaxDynamicSharedMemorySize,
                         SMEM_DYN);

    const int* src = ei;
    const int* dst = ei + NE;

    k_zero<<<(NN + 255) / 256, 256>>>();   // covers NN and GG*DD
    k_count<<<(NE + 255) / 256, 256>>>(dst);
    k_scanA<<<NCHUNK, CHUNK>>>();
    k_scanB<<<NCHUNK, CHUNK>>>();
    k_fill<<<(NE + 255) / 256, 256>>>(src, dst);

    int insel = 0;
    for (int l = 0; l < 5; l++) {
        int outsel = (insel == 1) ? 2 : 1;
        k_layer<<<(NN + 127) / 128, 256, SMEM_DYN>>>(
            x, insel, outsel,
            rel_w + l * DD * DD,
            root_w + l * DD * DD,
            rel_b + l * DD,
            (l >= 3) ? 1 : 0,
            (l == 4) ? 1 : 0,
            batch);
        insel = outsel;
    }

    k_final<<<GG, DD>>>(lin_w, lin_b, batch, out);
}